// round 10
// baseline (speedup 1.0000x reference)
#include <cuda_runtime.h>
#include <cstdint>

// FWHT over contiguous groups of 128 fp32 elements — final form.
// 8 lanes per group; each thread holds 16 CONTIGUOUS elements (2x 256-bit
// loads). Stages h=1,2,4,8 intra-thread; h=16,32,64 via shfl.xor deltas
// 1,2,4 (within 8-lane spans). 3 shuffles/element. Stores are evict-first
// (pure write stream); loads are plain non-coherent (hints showed no effect
// R7-R9). HBM-roofline bound: ~6.3-6.4 TB/s sustained on a 1:1 R/W stream.

__device__ __forceinline__ void ldg256(const float* p, float* r) {
    asm volatile(
        "ld.global.nc.v8.f32 {%0,%1,%2,%3,%4,%5,%6,%7}, [%8];"
        : "=f"(r[0]), "=f"(r[1]), "=f"(r[2]), "=f"(r[3]),
          "=f"(r[4]), "=f"(r[5]), "=f"(r[6]), "=f"(r[7])
        : "l"(p));
}

__device__ __forceinline__ void stg256_stream(float* p, const float* r) {
    asm volatile(
        "st.global.cs.v8.f32 [%0], {%1,%2,%3,%4,%5,%6,%7,%8};"
        :: "l"(p),
           "f"(r[0]), "f"(r[1]), "f"(r[2]), "f"(r[3]),
           "f"(r[4]), "f"(r[5]), "f"(r[6]), "f"(r[7])
        : "memory");
}

__global__ void __launch_bounds__(512) fwht128_kernel(
    const float* __restrict__ in, float* __restrict__ out)
{
    const unsigned int lane = threadIdx.x & 31u;
    // Each thread: 16 contiguous floats. Each warp: 512 floats = 4 groups.
    const unsigned int base = (blockIdx.x * 512u + threadIdx.x) * 16u;

    float e[16];
    ldg256(in + base, e);
    ldg256(in + base + 8u, e + 8);

    // Intra-thread stages h=1,2,4,8 (FWHT-16 on contiguous elements).
    float t;
    #pragma unroll
    for (int h = 1; h <= 8; h <<= 1) {
        #pragma unroll
        for (int i = 0; i < 16; ++i) {
            if ((i & h) == 0) {
                t = e[i];
                e[i]     = t + e[i + h];
                e[i + h] = t - e[i + h];
            }
        }
    }

    // Cross-lane stages h=16,32,64 -> shfl.xor deltas 1,2,4 (within 8 lanes).
    #pragma unroll
    for (int d = 1; d <= 4; d <<= 1) {
        bool up = (lane & (unsigned)d) != 0u;
        #pragma unroll
        for (int k = 0; k < 16; ++k) {
            float q = __shfl_xor_sync(0xffffffffu, e[k], d);
            e[k] = up ? (q - e[k]) : (e[k] + q);
        }
    }

    const float S = 0.08838834764831845f;  // 1/sqrt(128)
    float r[8];
    #pragma unroll
    for (int k = 0; k < 8; ++k) r[k] = e[k] * S;
    stg256_stream(out + base, r);
    #pragma unroll
    for (int k = 0; k < 8; ++k) r[k] = e[k + 8] * S;
    stg256_stream(out + base + 8u, r);
}

extern "C" void kernel_launch(void* const* d_in, const int* in_sizes, int n_in,
                              void* d_out, int out_size)
{
    const float* x = (const float*)d_in[0];
    float* y = (float*)d_out;
    unsigned int n = (unsigned int)in_sizes[0];   // 67108864
    unsigned int grid = n / (512u * 16u);         // = 8192, exact
    fwht128_kernel<<<grid, 512>>>(x, y);
}